// round 17
// baseline (speedup 1.0000x reference)
#include <cuda_runtime.h>
#include <math.h>
#include <stdint.h>

#define NSRC   2048
#define NGRID  50000
#define NLOCS  500
#define KTOP   5
#define NCELL  256          // 16x16 xy cells
#define CW     6.25f        // cell width (exact in fp32), 100/16
#define MARGIN 4.0f         // >> fp32 rounding slack (~0.05) in e units
#define FINF   __int_as_float(0x7f800000)
#define IBIG   0x7fffffff

// ---------------- device scratch ----------------
__device__ int    g_cnt[NCELL];
__device__ int    g_off[NCELL];
__device__ int    g_cur[NCELL];
__device__ float4 g_pts[NGRID];     // cell-sorted (x,y,z,w) scaled /1000
__device__ int    g_gid[NGRID];     // original grid index
__device__ int    g_topk[NSRC * KTOP];

__device__ __forceinline__ bool lexless(float a, int ai, float b, int bi) {
    return (a < b) || (a == b && ai < bi);
}
__device__ __forceinline__ float fsqrt_approx(float x) {
    float r;
    asm("sqrt.approx.f32 %0, %1;" : "=f"(r) : "f"(x));
    return r;
}
// identical expression in count & scatter -> identical cell assignment
__device__ __forceinline__ int cell_of(float x, float y) {
    int cx = min(15, (int)(x / CW));
    int cy = min(15, (int)(y / CW));
    return cy * 16 + cx;
}

// ============ K0: zero counters (globals persist across graph replays) ====
__global__ void init_kernel() { g_cnt[threadIdx.x] = 0; }

// ============ K1: per-cell counts (smem-aggregated histogram) =============
__global__ __launch_bounds__(256)
void count_kernel(const float* __restrict__ grid) {
    __shared__ int h[NCELL];
    const int t = threadIdx.x;
    h[t] = 0;
    __syncthreads();
    const int i = blockIdx.x * 256 + t;
    if (i < NGRID) {
        float x = grid[i * 3 + 0] / 1000.0f;
        float y = grid[i * 3 + 1] / 1000.0f;
        atomicAdd(&h[cell_of(x, y)], 1);
    }
    __syncthreads();
    if (h[t]) atomicAdd(&g_cnt[t], h[t]);
}

// ============ K2: exclusive prefix over 256 counts =========================
__global__ __launch_bounds__(256)
void scan_kernel() {
    __shared__ int tmp[NCELL];
    const int t = threadIdx.x;
    const int c = g_cnt[t];
    tmp[t] = c;
    __syncthreads();
    for (int off = 1; off < NCELL; off <<= 1) {
        int v = tmp[t];
        if (t >= off) v += tmp[t - off];
        __syncthreads();
        tmp[t] = v;
        __syncthreads();
    }
    g_off[t] = tmp[t] - c;
    g_cur[t] = tmp[t] - c;
}

// ============ K3: scatter points into cell-sorted order ====================
__global__ __launch_bounds__(256)
void scatter_kernel(const float* __restrict__ grid) {
    const int i = blockIdx.x * 256 + threadIdx.x;
    if (i >= NGRID) return;
    float x = grid[i * 3 + 0] / 1000.0f;
    float y = grid[i * 3 + 1] / 1000.0f;
    float z = grid[i * 3 + 2] / 1000.0f;
    float w = __fadd_rn(__fadd_rn(__fmul_rn(x, x), __fmul_rn(y, y)),
                        __fmul_rn(z, z));
    const int c   = cell_of(x, y);
    const int pos = atomicAdd(&g_cur[c], 1);
    g_pts[pos] = make_float4(x, y, z, w);
    g_gid[pos] = i;
}

// ============ K4: exact top-5 via best-first cell scan =====================
// block = one source, 256 threads. Each iteration: every warp picks the min-
// bound unscanned cell in its 32-cell range (global min = min of the 8);
// STOP (exact, margin-backed) when srv[4] <= min unscanned bound; else scan
// the 8 cells (coalesced float4), per-thread branchless sorted-5 insert,
// warp merge + warp0 merge (R14-proven machinery), fold into running top-5.
__global__ __launch_bounds__(256)
void topk_kernel(const float* __restrict__ src) {
    const int s = blockIdx.x, t = threadIdx.x;
    const int lane = t & 31, wid = t >> 5;

    __shared__ float sb[NCELL];
    __shared__ float swv[8 * KTOP];
    __shared__ int   swj[8 * KTOP];
    __shared__ int   scell[8], sstart[8], slen[8], spre[9];
    __shared__ float srv[KTOP];
    __shared__ int   srj[KTOP];
    __shared__ float snb;

    const float sx = src[s * 3 + 0] / 1000.0f;
    const float sy = src[s * 3 + 1] / 1000.0f;
    const float sz = src[s * 3 + 2] / 1000.0f;
    const float mx = -2.0f * sx, my = -2.0f * sy, mz = -2.0f * sz;
    const float s2 = sx * sx + sy * sy + sz * sz;

    {   // cell lower bound on computed e (margin-safe)
        const int cx = t & 15, cy = t >> 4;
        const float xlo = cx * CW, ylo = cy * CW;
        const float dx = fmaxf(0.0f, fmaxf(xlo - sx, sx - (xlo + CW)));
        const float dy = fmaxf(0.0f, fmaxf(ylo - sy, sy - (ylo + CW)));
        sb[t] = dx * dx + dy * dy - s2 - MARGIN;
    }
    if (t < KTOP) { srv[t] = FINF; srj[t] = IBIG; }
    __syncthreads();

    for (int iter = 0; iter < 32; iter++) {
        // per-warp argmin over its 32 cell bounds
        float bv = sb[t];
        int   bi = t;
#pragma unroll
        for (int off = 16; off > 0; off >>= 1) {
            float ov = __shfl_xor_sync(0xffffffffu, bv, off);
            int   oi = __shfl_xor_sync(0xffffffffu, bi, off);
            if (lexless(ov, oi, bv, bi)) { bv = ov; bi = oi; }
        }
        if (lane == 0) { swv[wid] = bv; scell[wid] = bi; }
        __syncthreads();
        if (t == 0) {
            float m = swv[0];
#pragma unroll
            for (int i = 1; i < 8; i++) m = fminf(m, swv[i]);
            snb = m;
            spre[0] = 0;
            for (int i = 0; i < 8; i++) {
                const int c = scell[i];
                const bool val = swv[i] < FINF;
                slen[i]   = val ? g_cnt[c] : 0;
                sstart[i] = g_off[c];
                spre[i + 1] = spre[i] + slen[i];
            }
        }
        if (t < 8) sb[scell[t]] = FINF;      // mark picked cells scanned
        __syncthreads();

        if (srv[KTOP - 1] <= snb) break;     // exact stop (margin-backed)

        const int TOT = spre[8];
        float cv[5];
        int   cj[5];
#pragma unroll
        for (int k = 0; k < 5; k++) { cv[k] = FINF; cj[k] = IBIG; }

        for (int p = t; p < TOT; p += 256) {
            int c = 0;
#pragma unroll
            for (int i = 1; i < 8; i++) if (p >= spre[i]) c = i;
            const int idx = sstart[c] + (p - spre[c]);
            const float4 P = g_pts[idx];
            const int    gi = g_gid[idx];
            const float e = fmaf(mx, P.x, fmaf(my, P.y, fmaf(mz, P.z, P.w)));
            // branchless sorted-5 insert
            if (lexless(e, gi, cv[4], cj[4])) { cv[4] = e; cj[4] = gi; }
#pragma unroll
            for (int a = 3; a >= 0; a--) {
                const bool sw = lexless(cv[a + 1], cj[a + 1], cv[a], cj[a]);
                const float tv = sw ? cv[a + 1] : cv[a];
                const float uv = sw ? cv[a] : cv[a + 1];
                const int   tg = sw ? cj[a + 1] : cj[a];
                const int   ug = sw ? cj[a] : cj[a + 1];
                cv[a] = tv; cv[a + 1] = uv; cj[a] = tg; cj[a + 1] = ug;
            }
        }

        // per-warp merge: top-5 over 32 sorted 5-lists
#pragma unroll
        for (int r = 0; r < KTOP; r++) {
            float wv2 = cv[0];
            int   wj2 = cj[0];
#pragma unroll
            for (int off = 16; off > 0; off >>= 1) {
                float ov = __shfl_xor_sync(0xffffffffu, wv2, off);
                int   oi = __shfl_xor_sync(0xffffffffu, wj2, off);
                if (lexless(ov, oi, wv2, wj2)) { wv2 = ov; wj2 = oi; }
            }
            if (lane == 0) { swv[wid * KTOP + r] = wv2; swj[wid * KTOP + r] = wj2; }
            if (cv[0] == wv2 && cj[0] == wj2) {   // real ids unique; pads benign
                cv[0] = cv[1]; cj[0] = cj[1]; cv[1] = cv[2]; cj[1] = cj[2];
                cv[2] = cv[3]; cj[2] = cj[3]; cv[3] = cv[4]; cj[3] = cj[4];
                cv[4] = FINF;  cj[4] = IBIG;
            }
        }
        __syncthreads();

        // warp 0: merge 8 sorted 5-lists, then fold into running top-5
        if (wid == 0) {
            float h0 = FINF, h1 = FINF, h2 = FINF, h3 = FINF, h4 = FINF;
            int   g0 = IBIG, g1 = IBIG, g2 = IBIG, g3 = IBIG, g4 = IBIG;
            if (lane < 8) {
                h0 = swv[lane * KTOP + 0]; g0 = swj[lane * KTOP + 0];
                h1 = swv[lane * KTOP + 1]; g1 = swj[lane * KTOP + 1];
                h2 = swv[lane * KTOP + 2]; g2 = swj[lane * KTOP + 2];
                h3 = swv[lane * KTOP + 3]; g3 = swj[lane * KTOP + 3];
                h4 = swv[lane * KTOP + 4]; g4 = swj[lane * KTOP + 4];
            }
            float iv[KTOP];
            int   ij[KTOP];
#pragma unroll
            for (int r = 0; r < KTOP; r++) {
                float wv2 = h0;
                int   wj2 = g0;
#pragma unroll
                for (int off = 16; off > 0; off >>= 1) {
                    float ov = __shfl_xor_sync(0xffffffffu, wv2, off);
                    int   oi = __shfl_xor_sync(0xffffffffu, wj2, off);
                    if (lexless(ov, oi, wv2, wj2)) { wv2 = ov; wj2 = oi; }
                }
                iv[r] = wv2; ij[r] = wj2;
                if (h0 == wv2 && g0 == wj2) {
                    h0 = h1; g0 = g1; h1 = h2; g1 = g2;
                    h2 = h3; g2 = g3; h3 = h4; g3 = g4;
                    h4 = FINF; g4 = IBIG;
                }
            }
            if (lane == 0) {   // two-pointer merge of sorted 5-lists (+sentinels)
                float av[6], bvv[6];
                int   aj[6], bj[6];
#pragma unroll
                for (int k = 0; k < KTOP; k++) {
                    av[k] = srv[k]; aj[k] = srj[k];
                    bvv[k] = iv[k]; bj[k] = ij[k];
                }
                av[5] = FINF; aj[5] = IBIG; bvv[5] = FINF; bj[5] = IBIG;
                float nv[KTOP];
                int   nj[KTOP];
                int ia = 0, ib = 0;
#pragma unroll
                for (int k = 0; k < KTOP; k++) {
                    const bool pa = lexless(av[ia], aj[ia], bvv[ib], bj[ib]);
                    nv[k] = pa ? av[ia] : bvv[ib];
                    nj[k] = pa ? aj[ia] : bj[ib];
                    if (pa) ia++; else ib++;
                }
#pragma unroll
                for (int k = 0; k < KTOP; k++) { srv[k] = nv[k]; srj[k] = nj[k]; }
            }
        }
        __syncthreads();
    }

    if (t < KTOP) g_topk[s * KTOP + t] = srj[t];
}

// ============ K5: fused tail — 4 sources per block (R8-exact) ==============
__global__ __launch_bounds__(512)
void tail_kernel(const float* __restrict__ src,
                 const int*   __restrict__ ind,
                 const float* __restrict__ log_amp,
                 const int*   __restrict__ phase,
                 const float* __restrict__ locs,
                 const float* __restrict__ mag_coef,
                 const float* __restrict__ eps_coef,
                 const float* __restrict__ dep_coef,
                 const float* __restrict__ bias,
                 float*       __restrict__ out) {
    const int s0  = blockIdx.x * 4;
    const int tid = threadIdx.x;

    __shared__ float bsum[4][NLOCS];
    __shared__ int   tks[4 * KTOP];

    if (tid < 4 * KTOP) tks[tid] = g_topk[s0 * KTOP + tid];
    __syncthreads();

    const int ph = phase[0];

    for (int task = tid; task < 4 * NLOCS; task += 512) {
        const int ss = task / NLOCS;
        const int j  = task - ss * NLOCS;
        const int col = j * 2 + ph;
        float acc = __ldg(&bias[(size_t)tks[ss * KTOP + 0] * (NLOCS * 2) + col]);
        acc += __ldg(&bias[(size_t)tks[ss * KTOP + 1] * (NLOCS * 2) + col]);
        acc += __ldg(&bias[(size_t)tks[ss * KTOP + 2] * (NLOCS * 2) + col]);
        acc += __ldg(&bias[(size_t)tks[ss * KTOP + 3] * (NLOCS * 2) + col]);
        acc += __ldg(&bias[(size_t)tks[ss * KTOP + 4] * (NLOCS * 2) + col]);
        bsum[ss][j] = acc / 5.0f;
    }
    __syncthreads();

    if (tid >= NLOCS) return;

    const float ec    = eps_coef[ph];
    const float dc    = dep_coef[ph];
    const float denom = fmaxf(mag_coef[ph], 1e-12f);

    const int li = ind[tid];
    const float lx = locs[li * 3 + 0];
    const float ly = locs[li * 3 + 1];
    const float lz = locs[li * 3 + 2];

#pragma unroll
    for (int ss = 0; ss < 4; ss++) {
        const int s = s0 + ss;
        const float sx = src[s * 3 + 0];
        const float sy = src[s * 3 + 1];
        const float sz = src[s * 3 + 2];

        const float dx = sx - lx;
        const float dy = sy - ly;
        const float d0  = fsqrt_approx(__fadd_rn(__fmul_rn(dx, dx),
                                                 __fmul_rn(dy, dy)));
        const float ld0 = __log10f(d0 + 1.0f);
        const float ldd = __log10f(fabsf(sz - lz) + 1.0f);

        const float b  = bsum[ss][li];
        const float la = log_amp[s * NLOCS + tid];
        out[s * NLOCS + tid] = (la - ec * ld0 - dc * ldd - b) / denom;
    }
}

// ---------------- launch ----------------
extern "C" void kernel_launch(void* const* d_in, const int* in_sizes, int n_in,
                              void* d_out, int out_size) {
    const float* src      = (const float*)d_in[0];
    const int*   ind      = (const int*)  d_in[1];
    const float* log_amp  = (const float*)d_in[2];
    const int*   phase    = (const int*)  d_in[3];
    const float* locs     = (const float*)d_in[4];
    const float* grid     = (const float*)d_in[5];
    const float* mag_coef = (const float*)d_in[6];
    const float* eps_coef = (const float*)d_in[7];
    const float* dep_coef = (const float*)d_in[8];
    const float* bias     = (const float*)d_in[9];
    float* out = (float*)d_out;

    const int nb = (NGRID + 255) / 256;   // 196

    init_kernel<<<1, 256>>>();
    count_kernel<<<nb, 256>>>(grid);
    scan_kernel<<<1, 256>>>();
    scatter_kernel<<<nb, 256>>>(grid);
    topk_kernel<<<NSRC, 256>>>(src);
    tail_kernel<<<NSRC / 4, 512>>>(src, ind, log_amp, phase, locs,
                                   mag_coef, eps_coef, dep_coef, bias, out);
}